// round 2
// baseline (speedup 1.0000x reference)
#include <cuda_runtime.h>
#include <math.h>

#define Bb 4
#define Nn 2048
#define Dd 512
#define Hh 8
#define HD 64
#define Mm (Bb * Nn)   // 8192
// scale * log2(e): scores computed directly in log2 domain
#define SC_LOG2E 0.18033688f   // 0.125 * 1.4426950408889634

// ---------------- scratch (no allocation allowed) ----------------
__device__ float g_Q[(size_t)Mm * Dd];
__device__ float g_K[(size_t)Mm * Dd];
__device__ float g_V[(size_t)Mm * Dd];
__device__ float g_Hh[(size_t)Mm * Dd];
__device__ float g_Y[(size_t)Mm * Dd];

// ---------------- fast exp2 for x <= 0, FMA-pipe only ----------------
__device__ __forceinline__ float exp2p(float x) {
    x = fmaxf(x, -126.0f);
    int e = __float2int_rd(x);
    float f = x - (float)e;          // f in [0,1)
    // Taylor of 2^f = e^{f ln2}, degree 6; max rel err ~1.5e-5
    float p = 1.5403530e-4f;
    p = fmaf(p, f, 1.3333558e-3f);
    p = fmaf(p, f, 9.6181291e-3f);
    p = fmaf(p, f, 5.5504109e-2f);
    p = fmaf(p, f, 2.4022651e-1f);
    p = fmaf(p, f, 6.9314718e-1f);
    p = fmaf(p, f, 1.0f);
    return p * __int_as_float((e + 127) << 23);
}

// ---------------- GEMM: C[M,N] = A[M,K] @ W[K,N] + bias (+ resid) ----------------
__global__ __launch_bounds__(256) void gemm_bias_kernel(
    const float* __restrict__ A, const float* __restrict__ W,
    const float* __restrict__ bias, const float* __restrict__ resid,
    float* __restrict__ C, int M, int N, int K)
{
    __shared__ float As[8][128];   // [k][m]
    __shared__ float Ws[8][128];   // [k][n]

    const int tid = threadIdx.x;
    const int bm = blockIdx.y;
    const int bn = blockIdx.x;
    const int tx = tid & 15;
    const int ty = tid >> 4;

    const float* Ablk = A + (size_t)bm * 128 * K;
    const float* Wblk = W + bn * 128;

    float acc[8][8];
#pragma unroll
    for (int i = 0; i < 8; i++)
#pragma unroll
        for (int j = 0; j < 8; j++) acc[i][j] = 0.f;

    for (int k0 = 0; k0 < K; k0 += 8) {
        {
            int r = tid >> 1, c = (tid & 1) * 4;
            float4 a = *(const float4*)(Ablk + (size_t)r * K + k0 + c);
            As[c + 0][r] = a.x; As[c + 1][r] = a.y;
            As[c + 2][r] = a.z; As[c + 3][r] = a.w;
        }
        {
            int r = tid >> 5, c = (tid & 31) * 4;
            *(float4*)&Ws[r][c] = *(const float4*)(Wblk + (size_t)(k0 + r) * N + c);
        }
        __syncthreads();

#pragma unroll
        for (int kk = 0; kk < 8; kk++) {
            float a[8], b[8];
            *(float4*)&a[0] = *(const float4*)&As[kk][ty * 8];
            *(float4*)&a[4] = *(const float4*)&As[kk][ty * 8 + 4];
            *(float4*)&b[0] = *(const float4*)&Ws[kk][tx * 8];
            *(float4*)&b[4] = *(const float4*)&Ws[kk][tx * 8 + 4];
#pragma unroll
            for (int i = 0; i < 8; i++)
#pragma unroll
                for (int j = 0; j < 8; j++)
                    acc[i][j] = fmaf(a[i], b[j], acc[i][j]);
        }
        __syncthreads();
    }

    const int col0 = bn * 128 + tx * 8;
#pragma unroll
    for (int i = 0; i < 8; i++) {
        int row = bm * 128 + ty * 8 + i;
        float* cp = C + (size_t)row * N + col0;
        const float* rp = resid ? (resid + (size_t)row * N + col0) : nullptr;
#pragma unroll
        for (int j = 0; j < 8; j += 4) {
            float4 o;
            o.x = acc[i][j + 0] + bias[col0 + j + 0];
            o.y = acc[i][j + 1] + bias[col0 + j + 1];
            o.z = acc[i][j + 2] + bias[col0 + j + 2];
            o.w = acc[i][j + 3] + bias[col0 + j + 3];
            if (rp) {
                float4 r4 = *(const float4*)(rp + j);
                o.x += r4.x; o.y += r4.y; o.z += r4.z; o.w += r4.w;
            }
            *(float4*)(cp + j) = o;
        }
    }
}

// ---------------- masked flash attention (log2-domain online softmax) ----------------
// grid: (N/128, H, B), 128 threads; one thread = one query row.
__global__ __launch_bounds__(128) void attn_kernel(
    const float* __restrict__ Q, const float* __restrict__ K,
    const float* __restrict__ V, const int* __restrict__ adj,
    float* __restrict__ O)
{
    __shared__ __align__(16) float Ksm[64][64];
    __shared__ __align__(16) float Vsm[64][64];

    const int tid = threadIdx.x;
    const int h = blockIdx.y;
    const int b = blockIdx.z;
    const int qi = blockIdx.x * 128 + tid;

    const float* qptr = Q + ((size_t)b * Nn + qi) * Dd + h * HD;
    float4 q4[16];
#pragma unroll
    for (int i = 0; i < 16; i++) q4[i] = ((const float4*)qptr)[i];

    float o[64];
#pragma unroll
    for (int d = 0; d < 64; d++) o[d] = 0.f;
    float m = -INFINITY, l = 0.f;    // m in log2 units

    const int* adjRow = adj + ((size_t)b * Nn + qi) * Nn;

    for (int k0 = 0; k0 < Nn; k0 += 64) {
        __syncthreads();
        {
            // coalesced tile load: float4 index f = i*128 + tid
#pragma unroll
            for (int i = 0; i < 8; i++) {
                int f = i * 128 + tid;
                int r = f >> 4, c = (f & 15) * 4;
                const size_t base = ((size_t)b * Nn + k0 + r) * Dd + h * HD + c;
                *(float4*)&Ksm[r][c] = *(const float4*)(K + base);
                *(float4*)&Vsm[r][c] = *(const float4*)(V + base);
            }
        }
        __syncthreads();

#pragma unroll 1
        for (int j0 = 0; j0 < 64; j0 += 4) {
            int4 msk = *(const int4*)(adjRow + k0 + j0);
            int mm[4] = {msk.x, msk.y, msk.z, msk.w};
#pragma unroll
            for (int u = 0; u < 4; u++) {
                if (!mm[u]) continue;
                const int j = j0 + u;
                const float4* krow = (const float4*)Ksm[j];
                // 4 independent FMA chains for ILP
                float s0 = 0.f, s1 = 0.f, s2 = 0.f, s3 = 0.f;
#pragma unroll
                for (int kk = 0; kk < 16; kk += 4) {
                    float4 k0v = krow[kk + 0];
                    float4 k1v = krow[kk + 1];
                    float4 k2v = krow[kk + 2];
                    float4 k3v = krow[kk + 3];
                    s0 = fmaf(q4[kk + 0].x, k0v.x, s0);
                    s0 = fmaf(q4[kk + 0].y, k0v.y, s0);
                    s0 = fmaf(q4[kk + 0].z, k0v.z, s0);
                    s0 = fmaf(q4[kk + 0].w, k0v.w, s0);
                    s1 = fmaf(q4[kk + 1].x, k1v.x, s1);
                    s1 = fmaf(q4[kk + 1].y, k1v.y, s1);
                    s1 = fmaf(q4[kk + 1].z, k1v.z, s1);
                    s1 = fmaf(q4[kk + 1].w, k1v.w, s1);
                    s2 = fmaf(q4[kk + 2].x, k2v.x, s2);
                    s2 = fmaf(q4[kk + 2].y, k2v.y, s2);
                    s2 = fmaf(q4[kk + 2].z, k2v.z, s2);
                    s2 = fmaf(q4[kk + 2].w, k2v.w, s2);
                    s3 = fmaf(q4[kk + 3].x, k3v.x, s3);
                    s3 = fmaf(q4[kk + 3].y, k3v.y, s3);
                    s3 = fmaf(q4[kk + 3].z, k3v.z, s3);
                    s3 = fmaf(q4[kk + 3].w, k3v.w, s3);
                }
                float s = ((s0 + s1) + (s2 + s3)) * SC_LOG2E;  // log2-domain score

                float p;
                if (s > m) {
                    float c = exp2p(m - s);   // ~0 on first hit (m=-inf)
                    l = fmaf(l, c, 1.0f);
#pragma unroll
                    for (int d = 0; d < 64; d++) o[d] *= c;
                    m = s;
                    p = 1.0f;
                } else {
                    p = exp2p(s - m);
                    l += p;
                }

                const float4* vrow = (const float4*)Vsm[j];
#pragma unroll
                for (int kk = 0; kk < 16; kk++) {
                    float4 vv = vrow[kk];
                    o[4 * kk + 0] = fmaf(p, vv.x, o[4 * kk + 0]);
                    o[4 * kk + 1] = fmaf(p, vv.y, o[4 * kk + 1]);
                    o[4 * kk + 2] = fmaf(p, vv.z, o[4 * kk + 2]);
                    o[4 * kk + 3] = fmaf(p, vv.w, o[4 * kk + 3]);
                }
            }
        }
    }

    const float inv = 1.f / l;
    float* optr = O + ((size_t)b * Nn + qi) * Dd + h * HD;
#pragma unroll
    for (int kk = 0; kk < 16; kk++) {
        float4 r;
        r.x = o[4 * kk + 0] * inv;
        r.y = o[4 * kk + 1] * inv;
        r.z = o[4 * kk + 2] * inv;
        r.w = o[4 * kk + 3] * inv;
        ((float4*)optr)[kk] = r;
    }
}

// ---------------- LayerNorm: one block per row ----------------
__global__ __launch_bounds__(128) void ln_kernel(
    const float* __restrict__ Y, const float* __restrict__ gamma,
    const float* __restrict__ beta, float* __restrict__ out)
{
    __shared__ float sbuf[4];
    __shared__ float smu, srstd;
    const int tid = threadIdx.x;
    const int row = blockIdx.x;
    const float* y = Y + (size_t)row * Dd;

    float4 v = ((const float4*)y)[tid];
    float sum = v.x + v.y + v.z + v.w;
    int lane = tid & 31, wid = tid >> 5;
#pragma unroll
    for (int off = 16; off > 0; off >>= 1) sum += __shfl_xor_sync(0xffffffffu, sum, off);
    if (lane == 0) sbuf[wid] = sum;
    __syncthreads();
    if (tid == 0) smu = (sbuf[0] + sbuf[1] + sbuf[2] + sbuf[3]) * (1.f / Dd);
    __syncthreads();
    float mu = smu;

    float dx = v.x - mu, dy = v.y - mu, dz = v.z - mu, dw = v.w - mu;
    float sq = dx * dx + dy * dy + dz * dz + dw * dw;
#pragma unroll
    for (int off = 16; off > 0; off >>= 1) sq += __shfl_xor_sync(0xffffffffu, sq, off);
    __syncthreads();
    if (lane == 0) sbuf[wid] = sq;
    __syncthreads();
    if (tid == 0) {
        float var = (sbuf[0] + sbuf[1] + sbuf[2] + sbuf[3]) * (1.f / Dd);
        srstd = rsqrtf(var + 1e-5f);
    }
    __syncthreads();
    float rstd = srstd;

    int c = tid * 4;
    float4 g = *(const float4*)(gamma + c);
    float4 be = *(const float4*)(beta + c);
    float4 r;
    r.x = dx * rstd * g.x + be.x;
    r.y = dy * rstd * g.y + be.y;
    r.z = dz * rstd * g.z + be.z;
    r.w = dw * rstd * g.w + be.w;
    ((float4*)(out + (size_t)row * Dd))[tid] = r;
}

// ---------------- launch ----------------
extern "C" void kernel_launch(void* const* d_in, const int* in_sizes, int n_in,
                              void* d_out, int out_size)
{
    const float* x     = (const float*)d_in[0];
    const int*   adj   = (const int*)d_in[1];
    const float* Wq    = (const float*)d_in[2];
    const float* bq    = (const float*)d_in[3];
    const float* Wk    = (const float*)d_in[4];
    const float* bk    = (const float*)d_in[5];
    const float* Wv    = (const float*)d_in[6];
    const float* bv    = (const float*)d_in[7];
    const float* Wo    = (const float*)d_in[8];
    const float* bo    = (const float*)d_in[9];
    const float* gamma = (const float*)d_in[10];
    const float* beta  = (const float*)d_in[11];
    float* out = (float*)d_out;

    float *Qb, *Kb, *Vb, *Hb, *Yb;
    cudaGetSymbolAddress((void**)&Qb, g_Q);
    cudaGetSymbolAddress((void**)&Kb, g_K);
    cudaGetSymbolAddress((void**)&Vb, g_V);
    cudaGetSymbolAddress((void**)&Hb, g_Hh);
    cudaGetSymbolAddress((void**)&Yb, g_Y);

    dim3 ggrid(Dd / 128, Mm / 128);   // (4, 64)
    gemm_bias_kernel<<<ggrid, 256>>>(x, Wq, bq, nullptr, Qb, Mm, Dd, Dd);
    gemm_bias_kernel<<<ggrid, 256>>>(x, Wk, bk, nullptr, Kb, Mm, Dd, Dd);
    gemm_bias_kernel<<<ggrid, 256>>>(x, Wv, bv, nullptr, Vb, Mm, Dd, Dd);

    dim3 agrid(Nn / 128, Hh, Bb);     // (16, 8, 4)
    attn_kernel<<<agrid, 128>>>(Qb, Kb, Vb, adj, Hb);

    gemm_bias_kernel<<<ggrid, 256>>>(Hb, Wo, bo, x, Yb, Mm, Dd, Dd);

    ln_kernel<<<Mm, 128>>>(Yb, gamma, beta, out);
}

// round 4
// speedup vs baseline: 2.3788x; 2.3788x over previous
#include <cuda_runtime.h>
#include <cstdint>
#include <math.h>

#define Bb 4
#define Nn 2048
#define Dd 512
#define Hh 8
#define HD 64
#define Mm (Bb * Nn)   // 8192
#define SC_LOG2E 0.18033688f   // 0.125 * log2(e)

// ---------------- scratch ----------------
__device__ float g_Q[(size_t)Mm * Dd];
__device__ float g_K[(size_t)Mm * Dd];
__device__ float g_V[(size_t)Mm * Dd];
__device__ float g_Hh[(size_t)Mm * Dd];
__device__ float g_Y[(size_t)Mm * Dd];

// ---------------- helpers ----------------
__device__ __forceinline__ float ex2(float x) {
    float y; asm("ex2.approx.f32 %0, %1;" : "=f"(y) : "f"(x)); return y;
}
__device__ __forceinline__ float tf32r(float f) {
    uint32_t u; asm("cvt.rna.tf32.f32 %0, %1;" : "=r"(u) : "f"(f));
    return __uint_as_float(u);
}
__device__ __forceinline__ void mma_tf32(float* c, const uint32_t* a, const uint32_t* b) {
    asm volatile("mma.sync.aligned.m16n8k8.row.col.f32.tf32.tf32.f32 "
        "{%0,%1,%2,%3}, {%4,%5,%6,%7}, {%8,%9}, {%0,%1,%2,%3};"
        : "+f"(c[0]), "+f"(c[1]), "+f"(c[2]), "+f"(c[3])
        : "r"(a[0]), "r"(a[1]), "r"(a[2]), "r"(a[3]), "r"(b[0]), "r"(b[1]));
}

#define STR 68          // SMEM row stride in floats (68*4 bytes; 16B aligned)
// SMEM float offsets
#define OFF_Q 0                       // [128][68]
#define OFF_K (128 * STR)             // [64][68]
#define OFF_V (OFF_K + 64 * STR)      // [64][68]
#define OFF_P (OFF_V + 64 * STR)      // 4 warps x [32][68]
#define ATTN_SMEM_FLOATS (OFF_P + 4 * 32 * STR)
#define ATTN_SMEM_BYTES (ATTN_SMEM_FLOATS * 4)   // 104448

// ================= mma.sync tf32 attention =================
// grid (16 q-tiles, 8 heads, 4 batch), 128 threads (4 warps, 32 q-rows each).
__global__ void __launch_bounds__(128, 2) attn_mma_kernel(
    const float* __restrict__ Q, const float* __restrict__ K,
    const float* __restrict__ V, const int* __restrict__ adj,
    float* __restrict__ O)
{
    extern __shared__ __align__(16) float sm[];
    const int tid = threadIdx.x;
    const int wid = tid >> 5, lane = tid & 31;
    const int g = lane >> 2, q = lane & 3;
    const int h = blockIdx.y, b = blockIdx.z;
    const int q0 = blockIdx.x * 128;

    // ---- fill Q tile (128 x 64), tf32-rounded ----
    {
        const float* qg = Q + ((size_t)(b * Nn + q0)) * Dd + h * HD;
#pragma unroll
        for (int i = 0; i < 16; i++) {
            int f = i * 128 + tid, r = f >> 4, c = (f & 15) * 4;
            float4 v4 = *(const float4*)(qg + (size_t)r * Dd + c);
            float* dst = sm + OFF_Q + r * STR + c;
            dst[0] = tf32r(v4.x); dst[1] = tf32r(v4.y);
            dst[2] = tf32r(v4.z); dst[3] = tf32r(v4.w);
        }
    }
    __syncthreads();

    float oacc[2][8][4];
#pragma unroll
    for (int t = 0; t < 2; t++)
#pragma unroll
        for (int n = 0; n < 8; n++)
#pragma unroll
            for (int i = 0; i < 4; i++) oacc[t][n][i] = 0.f;
    float lacc[4] = {0.f, 0.f, 0.f, 0.f};   // rows 16t+g, 16t+g+8

    float* Pw = sm + OFF_P + wid * 32 * STR;
    const float* Ks = sm + OFF_K;
    const float* Vs = sm + OFF_V;

#pragma unroll 1
    for (int t64 = 0; t64 < 32; t64++) {
        const int k0 = t64 * 64;
        __syncthreads();
        // ---- fill K, V tiles (64 x 64), tf32-rounded ----
        {
            const float* kg = K + ((size_t)(b * Nn + k0)) * Dd + h * HD;
            const float* vg = V + ((size_t)(b * Nn + k0)) * Dd + h * HD;
#pragma unroll
            for (int i = 0; i < 8; i++) {
                int f = i * 128 + tid, r = f >> 4, c = (f & 15) * 4;
                float4 kv = *(const float4*)(kg + (size_t)r * Dd + c);
                float* kd = sm + OFF_K + r * STR + c;
                kd[0] = tf32r(kv.x); kd[1] = tf32r(kv.y);
                kd[2] = tf32r(kv.z); kd[3] = tf32r(kv.w);
                float4 vv = *(const float4*)(vg + (size_t)r * Dd + c);
                float* vd = sm + OFF_V + r * STR + c;
                vd[0] = tf32r(vv.x); vd[1] = tf32r(vv.y);
                vd[2] = tf32r(vv.z); vd[3] = tf32r(vv.w);
            }
        }
        __syncthreads();

        // ---- S = Q(32x64) @ K^T(64x64) per warp ----
        float sacc[2][8][4];
#pragma unroll
        for (int t = 0; t < 2; t++)
#pragma unroll
            for (int n = 0; n < 8; n++)
#pragma unroll
                for (int i = 0; i < 4; i++) sacc[t][n][i] = 0.f;

#pragma unroll
        for (int kk = 0; kk < 8; kk++) {
            uint32_t a[2][4];
#pragma unroll
            for (int t = 0; t < 2; t++) {
                const float* qrow = sm + OFF_Q + (wid * 32 + 16 * t + g) * STR + 8 * kk + q;
                a[t][0] = __float_as_uint(qrow[0]);
                a[t][1] = __float_as_uint(qrow[8 * STR]);
                a[t][2] = __float_as_uint(qrow[4]);
                a[t][3] = __float_as_uint(qrow[8 * STR + 4]);
            }
            uint32_t bf[8][2];
#pragma unroll
            for (int n = 0; n < 8; n++) {
                const float* krow = Ks + (8 * n + g) * STR + 8 * kk + q;
                bf[n][0] = __float_as_uint(krow[0]);
                bf[n][1] = __float_as_uint(krow[4]);
            }
#pragma unroll
            for (int t = 0; t < 2; t++)
#pragma unroll
                for (int n = 0; n < 8; n++)
                    mma_tf32(sacc[t][n], a[t], bf[n]);
        }

        // ---- softmax: P = mask * exp2(S*sc); accumulate row sums; store P ----
#pragma unroll
        for (int t = 0; t < 2; t++) {
            const int rloc = 16 * t + g;                 // local row in warp tile
            const size_t arow = (size_t)(b * Nn + q0 + wid * 32 + rloc) * Nn + k0;
            const int* a0p = adj + arow;
            const int* a1p = adj + arow + (size_t)8 * Nn;
            float l01 = 0.f, l23 = 0.f;
#pragma unroll
            for (int n = 0; n < 8; n++) {
                int2 m0 = *(const int2*)(a0p + 8 * n + 2 * q);
                int2 m1 = *(const int2*)(a1p + 8 * n + 2 * q);
                float p0 = m0.x ? ex2(sacc[t][n][0] * SC_LOG2E) : 0.f;
                float p1 = m0.y ? ex2(sacc[t][n][1] * SC_LOG2E) : 0.f;
                float p2 = m1.x ? ex2(sacc[t][n][2] * SC_LOG2E) : 0.f;
                float p3 = m1.y ? ex2(sacc[t][n][3] * SC_LOG2E) : 0.f;
                l01 += p0 + p1; l23 += p2 + p3;
                float2 w0; w0.x = tf32r(p0); w0.y = tf32r(p1);
                float2 w1; w1.x = tf32r(p2); w1.y = tf32r(p3);
                *(float2*)(Pw + rloc * STR + 8 * n + 2 * q) = w0;
                *(float2*)(Pw + (rloc + 8) * STR + 8 * n + 2 * q) = w1;
            }
            lacc[2 * t + 0] += l01;
            lacc[2 * t + 1] += l23;
        }
        __syncwarp();

        // ---- O += P(32x64) @ V(64x64) ----
#pragma unroll
        for (int kk = 0; kk < 8; kk++) {
            uint32_t a[2][4];
#pragma unroll
            for (int t = 0; t < 2; t++) {
                const float* prow = Pw + (16 * t + g) * STR + 8 * kk + q;
                a[t][0] = __float_as_uint(prow[0]);
                a[t][1] = __float_as_uint(prow[8 * STR]);
                a[t][2] = __float_as_uint(prow[4]);
                a[t][3] = __float_as_uint(prow[8 * STR + 4]);
            }
            uint32_t bf[8][2];
#pragma unroll
            for (int n = 0; n < 8; n++) {
                const float* vrow = Vs + (8 * kk + q) * STR + 8 * n + g;
                bf[n][0] = __float_as_uint(vrow[0]);
                bf[n][1] = __float_as_uint(vrow[4 * STR]);
            }
#pragma unroll
            for (int t = 0; t < 2; t++)
#pragma unroll
                for (int n = 0; n < 8; n++)
                    mma_tf32(oacc[t][n], a[t], bf[n]);
        }
        __syncwarp();
    }

    // ---- reduce row sums across the quad (lanes sharing g) ----
#pragma unroll
    for (int i = 0; i < 4; i++) {
        lacc[i] += __shfl_xor_sync(0xffffffffu, lacc[i], 1);
        lacc[i] += __shfl_xor_sync(0xffffffffu, lacc[i], 2);
    }
    float inv[4];
#pragma unroll
    for (int i = 0; i < 4; i++) inv[i] = 1.f / lacc[i];

    // ---- write O ----
    float* og = O + ((size_t)(b * Nn + q0 + wid * 32)) * Dd + h * HD;
#pragma unroll
    for (int t = 0; t < 2; t++) {
        const int rloc = 16 * t + g;
#pragma unroll
        for (int n = 0; n < 8; n++) {
            float2 w0;
            w0.x = oacc[t][n][0] * inv[2 * t];
            w0.y = oacc[t][n][1] * inv[2 * t];
            *(float2*)(og + (size_t)rloc * Dd + 8 * n + 2 * q) = w0;
            float2 w1;
            w1.x = oacc[t][n][2] * inv[2 * t + 1];
            w1.y = oacc[t][n][3] * inv[2 * t + 1];
            *(float2*)(og + (size_t)(rloc + 8) * Dd + 8 * n + 2 * q) = w1;
        }
    }
}

// ================= scalar GEMM (unchanged) =================
__global__ __launch_bounds__(256) void gemm_bias_kernel(
    const float* __restrict__ A, const float* __restrict__ W,
    const float* __restrict__ bias, const float* __restrict__ resid,
    float* __restrict__ C, int M, int N, int K)
{
    __shared__ float As[8][128];
    __shared__ float Ws[8][128];

    const int tid = threadIdx.x;
    const int bm = blockIdx.y, bn = blockIdx.x;
    const int tx = tid & 15, ty = tid >> 4;

    const float* Ablk = A + (size_t)bm * 128 * K;
    const float* Wblk = W + bn * 128;

    float acc[8][8];
#pragma unroll
    for (int i = 0; i < 8; i++)
#pragma unroll
        for (int j = 0; j < 8; j++) acc[i][j] = 0.f;

    for (int k0 = 0; k0 < K; k0 += 8) {
        {
            int r = tid >> 1, c = (tid & 1) * 4;
            float4 a = *(const float4*)(Ablk + (size_t)r * K + k0 + c);
            As[c + 0][r] = a.x; As[c + 1][r] = a.y;
            As[c + 2][r] = a.z; As[c + 3][r] = a.w;
        }
        {
            int r = tid >> 5, c = (tid & 31) * 4;
            *(float4*)&Ws[r][c] = *(const float4*)(Wblk + (size_t)(k0 + r) * N + c);
        }
        __syncthreads();
#pragma unroll
        for (int kk = 0; kk < 8; kk++) {
            float a[8], bb[8];
            *(float4*)&a[0] = *(const float4*)&As[kk][ty * 8];
            *(float4*)&a[4] = *(const float4*)&As[kk][ty * 8 + 4];
            *(float4*)&bb[0] = *(const float4*)&Ws[kk][tx * 8];
            *(float4*)&bb[4] = *(const float4*)&Ws[kk][tx * 8 + 4];
#pragma unroll
            for (int i = 0; i < 8; i++)
#pragma unroll
                for (int j = 0; j < 8; j++)
                    acc[i][j] = fmaf(a[i], bb[j], acc[i][j]);
        }
        __syncthreads();
    }

    const int col0 = bn * 128 + tx * 8;
#pragma unroll
    for (int i = 0; i < 8; i++) {
        int row = bm * 128 + ty * 8 + i;
        float* cp = C + (size_t)row * N + col0;
        const float* rp = resid ? (resid + (size_t)row * N + col0) : nullptr;
#pragma unroll
        for (int j = 0; j < 8; j += 4) {
            float4 o;
            o.x = acc[i][j + 0] + bias[col0 + j + 0];
            o.y = acc[i][j + 1] + bias[col0 + j + 1];
            o.z = acc[i][j + 2] + bias[col0 + j + 2];
            o.w = acc[i][j + 3] + bias[col0 + j + 3];
            if (rp) {
                float4 r4 = *(const float4*)(rp + j);
                o.x += r4.x; o.y += r4.y; o.z += r4.z; o.w += r4.w;
            }
            *(float4*)(cp + j) = o;
        }
    }
}

// ================= LayerNorm (unchanged) =================
__global__ __launch_bounds__(128) void ln_kernel(
    const float* __restrict__ Y, const float* __restrict__ gamma,
    const float* __restrict__ beta, float* __restrict__ out)
{
    __shared__ float sbuf[4];
    __shared__ float smu, srstd;
    const int tid = threadIdx.x;
    const int row = blockIdx.x;
    const float* y = Y + (size_t)row * Dd;

    float4 v = ((const float4*)y)[tid];
    float sum = v.x + v.y + v.z + v.w;
    int lane = tid & 31, wid = tid >> 5;
#pragma unroll
    for (int off = 16; off > 0; off >>= 1) sum += __shfl_xor_sync(0xffffffffu, sum, off);
    if (lane == 0) sbuf[wid] = sum;
    __syncthreads();
    if (tid == 0) smu = (sbuf[0] + sbuf[1] + sbuf[2] + sbuf[3]) * (1.f / Dd);
    __syncthreads();
    float mu = smu;

    float dx = v.x - mu, dy = v.y - mu, dz = v.z - mu, dw = v.w - mu;
    float sq = dx * dx + dy * dy + dz * dz + dw * dw;
#pragma unroll
    for (int off = 16; off > 0; off >>= 1) sq += __shfl_xor_sync(0xffffffffu, sq, off);
    __syncthreads();
    if (lane == 0) sbuf[wid] = sq;
    __syncthreads();
    if (tid == 0) {
        float var = (sbuf[0] + sbuf[1] + sbuf[2] + sbuf[3]) * (1.f / Dd);
        srstd = rsqrtf(var + 1e-5f);
    }
    __syncthreads();
    float rstd = srstd;

    int c = tid * 4;
    float4 g = *(const float4*)(gamma + c);
    float4 be = *(const float4*)(beta + c);
    float4 r;
    r.x = dx * rstd * g.x + be.x;
    r.y = dy * rstd * g.y + be.y;
    r.z = dz * rstd * g.z + be.z;
    r.w = dw * rstd * g.w + be.w;
    ((float4*)(out + (size_t)row * Dd))[tid] = r;
}

// ================= launch =================
extern "C" void kernel_launch(void* const* d_in, const int* in_sizes, int n_in,
                              void* d_out, int out_size)
{
    const float* x     = (const float*)d_in[0];
    const int*   adj   = (const int*)d_in[1];
    const float* Wq    = (const float*)d_in[2];
    const float* bq    = (const float*)d_in[3];
    const float* Wk    = (const float*)d_in[4];
    const float* bk    = (const float*)d_in[5];
    const float* Wv    = (const float*)d_in[6];
    const float* bv    = (const float*)d_in[7];
    const float* Wo    = (const float*)d_in[8];
    const float* bo    = (const float*)d_in[9];
    const float* gamma = (const float*)d_in[10];
    const float* beta  = (const float*)d_in[11];
    float* out = (float*)d_out;

    float *Qb, *Kb, *Vb, *Hb, *Yb;
    cudaGetSymbolAddress((void**)&Qb, g_Q);
    cudaGetSymbolAddress((void**)&Kb, g_K);
    cudaGetSymbolAddress((void**)&Vb, g_V);
    cudaGetSymbolAddress((void**)&Hb, g_Hh);
    cudaGetSymbolAddress((void**)&Yb, g_Y);

    cudaFuncSetAttribute(attn_mma_kernel, cudaFuncAttributeMaxDynamicSharedMemorySize, ATTN_SMEM_BYTES);

    dim3 ggrid(Dd / 128, Mm / 128);
    gemm_bias_kernel<<<ggrid, 256>>>(x, Wq, bq, nullptr, Qb, Mm, Dd, Dd);
    gemm_bias_kernel<<<ggrid, 256>>>(x, Wk, bk, nullptr, Kb, Mm, Dd, Dd);
    gemm_bias_kernel<<<ggrid, 256>>>(x, Wv, bv, nullptr, Vb, Mm, Dd, Dd);

    dim3 agrid(Nn / 128, Hh, Bb);     // (16, 8, 4)
    attn_mma_kernel<<<agrid, 128, ATTN_SMEM_BYTES>>>(Qb, Kb, Vb, adj, Hb);

    gemm_bias_kernel<<<ggrid, 256>>>(Hb, Wo, bo, x, Yb, Mm, Dd, Dd);

    ln_kernel<<<Mm, 128>>>(Yb, gamma, beta, out);
}

// round 5
// speedup vs baseline: 3.1594x; 1.3282x over previous
#include <cuda_runtime.h>
#include <cstdint>
#include <math.h>

#define Bb 4
#define Nn 2048
#define Dd 512
#define Hh 8
#define HD 64
#define Mm (Bb * Nn)   // 8192
#define SC_LOG2E 0.18033688f   // 0.125 * log2(e)

// ---------------- scratch ----------------
__device__ float g_Q[(size_t)Mm * Dd];
__device__ float g_K[(size_t)Mm * Dd];
__device__ float g_V[(size_t)Mm * Dd];
__device__ float g_Hh[(size_t)Mm * Dd];
__device__ float g_Y[(size_t)Mm * Dd];

// ---------------- helpers ----------------
__device__ __forceinline__ float ex2(float x) {
    float y; asm("ex2.approx.f32 %0, %1;" : "=f"(y) : "f"(x)); return y;
}
__device__ __forceinline__ float tf32r(float f) {
    uint32_t u; asm("cvt.rna.tf32.f32 %0, %1;" : "=r"(u) : "f"(f));
    return __uint_as_float(u);
}
__device__ __forceinline__ void mma_tf32(float* c, const uint32_t* a, const uint32_t* b) {
    asm volatile("mma.sync.aligned.m16n8k8.row.col.f32.tf32.tf32.f32 "
        "{%0,%1,%2,%3}, {%4,%5,%6,%7}, {%8,%9}, {%0,%1,%2,%3};"
        : "+f"(c[0]), "+f"(c[1]), "+f"(c[2]), "+f"(c[3])
        : "r"(a[0]), "r"(a[1]), "r"(a[2]), "r"(a[3]), "r"(b[0]), "r"(b[1]));
}

// ======================================================================
// tf32 mma GEMM: C[M,N] = A[M,K] @ W[K,N] + bias (+ resid)
// BM=128, BN=64, BK=32, 256 threads (8 warps: 4 along M x 2 along N),
// warp tile 32x32.
// ======================================================================
#define GBM 128
#define GBN 64
#define GBK 32
#define ASTR 36   // As row stride (floats): bank = 4g+q, conflict-free frags
#define BSTR 68   // Ws row stride (floats): bank = 4q+g, conflict-free frags

__global__ void __launch_bounds__(256, 3) gemm_mma_kernel(
    const float* __restrict__ A, const float* __restrict__ W,
    const float* __restrict__ bias, const float* __restrict__ resid,
    float* __restrict__ C, int M, int N, int K)
{
    __shared__ __align__(16) float As[GBM * ASTR];   // [m][k]
    __shared__ __align__(16) float Ws[GBK * BSTR];   // [k][n]

    const int tid = threadIdx.x;
    const int wid = tid >> 5, lane = tid & 31;
    const int g = lane >> 2, q = lane & 3;
    const int wm = wid & 3, wn = wid >> 2;         // warp coords
    const int m0 = blockIdx.y * GBM;
    const int n0 = blockIdx.x * GBN;

    float acc[2][4][4];
#pragma unroll
    for (int t = 0; t < 2; t++)
#pragma unroll
        for (int nb = 0; nb < 4; nb++)
#pragma unroll
            for (int i = 0; i < 4; i++) acc[t][nb][i] = 0.f;

    for (int k0 = 0; k0 < K; k0 += GBK) {
        // ---- stage A tile: 128 x 32 (1024 float4, 4 per thread) ----
#pragma unroll
        for (int i = 0; i < 4; i++) {
            int idx = i * 256 + tid;
            int r = idx >> 3, c4 = (idx & 7) * 4;
            float4 a4 = *(const float4*)(A + (size_t)(m0 + r) * K + k0 + c4);
            float* d = As + r * ASTR + c4;
            d[0] = tf32r(a4.x); d[1] = tf32r(a4.y);
            d[2] = tf32r(a4.z); d[3] = tf32r(a4.w);
        }
        // ---- stage W tile: 32 x 64 (512 float4, 2 per thread) ----
#pragma unroll
        for (int i = 0; i < 2; i++) {
            int idx = i * 256 + tid;
            int r = idx >> 4, c4 = (idx & 15) * 4;
            float4 w4 = *(const float4*)(W + (size_t)(k0 + r) * N + n0 + c4);
            float* d = Ws + r * BSTR + c4;
            d[0] = tf32r(w4.x); d[1] = tf32r(w4.y);
            d[2] = tf32r(w4.z); d[3] = tf32r(w4.w);
        }
        __syncthreads();

#pragma unroll
        for (int kk = 0; kk < 4; kk++) {
            uint32_t a[2][4];
#pragma unroll
            for (int t = 0; t < 2; t++) {
                const float* ar = As + (wm * 32 + 16 * t + g) * ASTR + 8 * kk + q;
                a[t][0] = __float_as_uint(ar[0]);
                a[t][1] = __float_as_uint(ar[8 * ASTR]);
                a[t][2] = __float_as_uint(ar[4]);
                a[t][3] = __float_as_uint(ar[8 * ASTR + 4]);
            }
            uint32_t bf[4][2];
#pragma unroll
            for (int nb = 0; nb < 4; nb++) {
                const float* br = Ws + (8 * kk + q) * BSTR + wn * 32 + 8 * nb + g;
                bf[nb][0] = __float_as_uint(br[0]);
                bf[nb][1] = __float_as_uint(br[4 * BSTR]);
            }
#pragma unroll
            for (int t = 0; t < 2; t++)
#pragma unroll
                for (int nb = 0; nb < 4; nb++)
                    mma_tf32(acc[t][nb], a[t], bf[nb]);
        }
        __syncthreads();
    }

    // ---- epilogue: bias (+resid), write float2 pairs ----
#pragma unroll
    for (int t = 0; t < 2; t++) {
        const int r0 = m0 + wm * 32 + 16 * t + g;
#pragma unroll
        for (int nb = 0; nb < 4; nb++) {
            const int c = n0 + wn * 32 + 8 * nb + 2 * q;
            float bx = bias[c], by = bias[c + 1];
            float2 w0, w1;
            w0.x = acc[t][nb][0] + bx; w0.y = acc[t][nb][1] + by;
            w1.x = acc[t][nb][2] + bx; w1.y = acc[t][nb][3] + by;
            if (resid) {
                float2 r4 = *(const float2*)(resid + (size_t)r0 * N + c);
                float2 r5 = *(const float2*)(resid + (size_t)(r0 + 8) * N + c);
                w0.x += r4.x; w0.y += r4.y;
                w1.x += r5.x; w1.y += r5.y;
            }
            *(float2*)(C + (size_t)r0 * N + c) = w0;
            *(float2*)(C + (size_t)(r0 + 8) * N + c) = w1;
        }
    }
}

// ================= mma.sync tf32 attention (unchanged from R4) =================
#define STR 68
#define OFF_Q 0
#define OFF_K (128 * STR)
#define OFF_V (OFF_K + 64 * STR)
#define OFF_P (OFF_V + 64 * STR)
#define ATTN_SMEM_FLOATS (OFF_P + 4 * 32 * STR)
#define ATTN_SMEM_BYTES (ATTN_SMEM_FLOATS * 4)   // 104448

__global__ void __launch_bounds__(128, 2) attn_mma_kernel(
    const float* __restrict__ Q, const float* __restrict__ K,
    const float* __restrict__ V, const int* __restrict__ adj,
    float* __restrict__ O)
{
    extern __shared__ __align__(16) float sm[];
    const int tid = threadIdx.x;
    const int wid = tid >> 5, lane = tid & 31;
    const int g = lane >> 2, q = lane & 3;
    const int h = blockIdx.y, b = blockIdx.z;
    const int q0 = blockIdx.x * 128;

    {
        const float* qg = Q + ((size_t)(b * Nn + q0)) * Dd + h * HD;
#pragma unroll
        for (int i = 0; i < 16; i++) {
            int f = i * 128 + tid, r = f >> 4, c = (f & 15) * 4;
            float4 v4 = *(const float4*)(qg + (size_t)r * Dd + c);
            float* dst = sm + OFF_Q + r * STR + c;
            dst[0] = tf32r(v4.x); dst[1] = tf32r(v4.y);
            dst[2] = tf32r(v4.z); dst[3] = tf32r(v4.w);
        }
    }
    __syncthreads();

    float oacc[2][8][4];
#pragma unroll
    for (int t = 0; t < 2; t++)
#pragma unroll
        for (int n = 0; n < 8; n++)
#pragma unroll
            for (int i = 0; i < 4; i++) oacc[t][n][i] = 0.f;
    float lacc[4] = {0.f, 0.f, 0.f, 0.f};

    float* Pw = sm + OFF_P + wid * 32 * STR;
    const float* Ks = sm + OFF_K;
    const float* Vs = sm + OFF_V;

#pragma unroll 1
    for (int t64 = 0; t64 < 32; t64++) {
        const int k0 = t64 * 64;
        __syncthreads();
        {
            const float* kg = K + ((size_t)(b * Nn + k0)) * Dd + h * HD;
            const float* vg = V + ((size_t)(b * Nn + k0)) * Dd + h * HD;
#pragma unroll
            for (int i = 0; i < 8; i++) {
                int f = i * 128 + tid, r = f >> 4, c = (f & 15) * 4;
                float4 kv = *(const float4*)(kg + (size_t)r * Dd + c);
                float* kd = sm + OFF_K + r * STR + c;
                kd[0] = tf32r(kv.x); kd[1] = tf32r(kv.y);
                kd[2] = tf32r(kv.z); kd[3] = tf32r(kv.w);
                float4 vv = *(const float4*)(vg + (size_t)r * Dd + c);
                float* vd = sm + OFF_V + r * STR + c;
                vd[0] = tf32r(vv.x); vd[1] = tf32r(vv.y);
                vd[2] = tf32r(vv.z); vd[3] = tf32r(vv.w);
            }
        }
        __syncthreads();

        float sacc[2][8][4];
#pragma unroll
        for (int t = 0; t < 2; t++)
#pragma unroll
            for (int n = 0; n < 8; n++)
#pragma unroll
                for (int i = 0; i < 4; i++) sacc[t][n][i] = 0.f;

#pragma unroll
        for (int kk = 0; kk < 8; kk++) {
            uint32_t a[2][4];
#pragma unroll
            for (int t = 0; t < 2; t++) {
                const float* qrow = sm + OFF_Q + (wid * 32 + 16 * t + g) * STR + 8 * kk + q;
                a[t][0] = __float_as_uint(qrow[0]);
                a[t][1] = __float_as_uint(qrow[8 * STR]);
                a[t][2] = __float_as_uint(qrow[4]);
                a[t][3] = __float_as_uint(qrow[8 * STR + 4]);
            }
            uint32_t bf[8][2];
#pragma unroll
            for (int n = 0; n < 8; n++) {
                const float* krow = Ks + (8 * n + g) * STR + 8 * kk + q;
                bf[n][0] = __float_as_uint(krow[0]);
                bf[n][1] = __float_as_uint(krow[4]);
            }
#pragma unroll
            for (int t = 0; t < 2; t++)
#pragma unroll
                for (int n = 0; n < 8; n++)
                    mma_tf32(sacc[t][n], a[t], bf[n]);
        }

#pragma unroll
        for (int t = 0; t < 2; t++) {
            const int rloc = 16 * t + g;
            const size_t arow = (size_t)(b * Nn + q0 + wid * 32 + rloc) * Nn + k0;
            const int* a0p = adj + arow;
            const int* a1p = adj + arow + (size_t)8 * Nn;
            float l01 = 0.f, l23 = 0.f;
#pragma unroll
            for (int n = 0; n < 8; n++) {
                int2 m0 = *(const int2*)(a0p + 8 * n + 2 * q);
                int2 m1 = *(const int2*)(a1p + 8 * n + 2 * q);
                float p0 = m0.x ? ex2(sacc[t][n][0] * SC_LOG2E) : 0.f;
                float p1 = m0.y ? ex2(sacc[t][n][1] * SC_LOG2E) : 0.f;
                float p2 = m1.x ? ex2(sacc[t][n][2] * SC_LOG2E) : 0.f;
                float p3 = m1.y ? ex2(sacc[t][n][3] * SC_LOG2E) : 0.f;
                l01 += p0 + p1; l23 += p2 + p3;
                float2 w0; w0.x = tf32r(p0); w0.y = tf32r(p1);
                float2 w1; w1.x = tf32r(p2); w1.y = tf32r(p3);
                *(float2*)(Pw + rloc * STR + 8 * n + 2 * q) = w0;
                *(float2*)(Pw + (rloc + 8) * STR + 8 * n + 2 * q) = w1;
            }
            lacc[2 * t + 0] += l01;
            lacc[2 * t + 1] += l23;
        }
        __syncwarp();

#pragma unroll
        for (int kk = 0; kk < 8; kk++) {
            uint32_t a[2][4];
#pragma unroll
            for (int t = 0; t < 2; t++) {
                const float* prow = Pw + (16 * t + g) * STR + 8 * kk + q;
                a[t][0] = __float_as_uint(prow[0]);
                a[t][1] = __float_as_uint(prow[8 * STR]);
                a[t][2] = __float_as_uint(prow[4]);
                a[t][3] = __float_as_uint(prow[8 * STR + 4]);
            }
            uint32_t bf[8][2];
#pragma unroll
            for (int n = 0; n < 8; n++) {
                const float* vrow = Vs + (8 * kk + q) * STR + 8 * n + g;
                bf[n][0] = __float_as_uint(vrow[0]);
                bf[n][1] = __float_as_uint(vrow[4 * STR]);
            }
#pragma unroll
            for (int t = 0; t < 2; t++)
#pragma unroll
                for (int n = 0; n < 8; n++)
                    mma_tf32(oacc[t][n], a[t], bf[n]);
        }
        __syncwarp();
    }

#pragma unroll
    for (int i = 0; i < 4; i++) {
        lacc[i] += __shfl_xor_sync(0xffffffffu, lacc[i], 1);
        lacc[i] += __shfl_xor_sync(0xffffffffu, lacc[i], 2);
    }
    float inv[4];
#pragma unroll
    for (int i = 0; i < 4; i++) inv[i] = 1.f / lacc[i];

    float* og = O + ((size_t)(b * Nn + q0 + wid * 32)) * Dd + h * HD;
#pragma unroll
    for (int t = 0; t < 2; t++) {
        const int rloc = 16 * t + g;
#pragma unroll
        for (int n = 0; n < 8; n++) {
            float2 w0;
            w0.x = oacc[t][n][0] * inv[2 * t];
            w0.y = oacc[t][n][1] * inv[2 * t];
            *(float2*)(og + (size_t)rloc * Dd + 8 * n + 2 * q) = w0;
            float2 w1;
            w1.x = oacc[t][n][2] * inv[2 * t + 1];
            w1.y = oacc[t][n][3] * inv[2 * t + 1];
            *(float2*)(og + (size_t)(rloc + 8) * Dd + 8 * n + 2 * q) = w1;
        }
    }
}

// ================= LayerNorm (unchanged) =================
__global__ __launch_bounds__(128) void ln_kernel(
    const float* __restrict__ Y, const float* __restrict__ gamma,
    const float* __restrict__ beta, float* __restrict__ out)
{
    __shared__ float sbuf[4];
    __shared__ float smu, srstd;
    const int tid = threadIdx.x;
    const int row = blockIdx.x;
    const float* y = Y + (size_t)row * Dd;

    float4 v = ((const float4*)y)[tid];
    float sum = v.x + v.y + v.z + v.w;
    int lane = tid & 31, wid = tid >> 5;
#pragma unroll
    for (int off = 16; off > 0; off >>= 1) sum += __shfl_xor_sync(0xffffffffu, sum, off);
    if (lane == 0) sbuf[wid] = sum;
    __syncthreads();
    if (tid == 0) smu = (sbuf[0] + sbuf[1] + sbuf[2] + sbuf[3]) * (1.f / Dd);
    __syncthreads();
    float mu = smu;

    float dx = v.x - mu, dy = v.y - mu, dz = v.z - mu, dw = v.w - mu;
    float sq = dx * dx + dy * dy + dz * dz + dw * dw;
#pragma unroll
    for (int off = 16; off > 0; off >>= 1) sq += __shfl_xor_sync(0xffffffffu, sq, off);
    __syncthreads();
    if (lane == 0) sbuf[wid] = sq;
    __syncthreads();
    if (tid == 0) {
        float var = (sbuf[0] + sbuf[1] + sbuf[2] + sbuf[3]) * (1.f / Dd);
        srstd = rsqrtf(var + 1e-5f);
    }
    __syncthreads();
    float rstd = srstd;

    int c = tid * 4;
    float4 g = *(const float4*)(gamma + c);
    float4 be = *(const float4*)(beta + c);
    float4 r;
    r.x = dx * rstd * g.x + be.x;
    r.y = dy * rstd * g.y + be.y;
    r.z = dz * rstd * g.z + be.z;
    r.w = dw * rstd * g.w + be.w;
    ((float4*)(out + (size_t)row * Dd))[tid] = r;
}

// ================= launch =================
extern "C" void kernel_launch(void* const* d_in, const int* in_sizes, int n_in,
                              void* d_out, int out_size)
{
    const float* x     = (const float*)d_in[0];
    const int*   adj   = (const int*)d_in[1];
    const float* Wq    = (const float*)d_in[2];
    const float* bq    = (const float*)d_in[3];
    const float* Wk    = (const float*)d_in[4];
    const float* bk    = (const float*)d_in[5];
    const float* Wv    = (const float*)d_in[6];
    const float* bv    = (const float*)d_in[7];
    const float* Wo    = (const float*)d_in[8];
    const float* bo    = (const float*)d_in[9];
    const float* gamma = (const float*)d_in[10];
    const float* beta  = (const float*)d_in[11];
    float* out = (float*)d_out;

    float *Qb, *Kb, *Vb, *Hb, *Yb;
    cudaGetSymbolAddress((void**)&Qb, g_Q);
    cudaGetSymbolAddress((void**)&Kb, g_K);
    cudaGetSymbolAddress((void**)&Vb, g_V);
    cudaGetSymbolAddress((void**)&Hb, g_Hh);
    cudaGetSymbolAddress((void**)&Yb, g_Y);

    cudaFuncSetAttribute(attn_mma_kernel, cudaFuncAttributeMaxDynamicSharedMemorySize, ATTN_SMEM_BYTES);

    dim3 ggrid(Dd / GBN, Mm / GBM);   // (8, 64)
    gemm_mma_kernel<<<ggrid, 256>>>(x, Wq, bq, nullptr, Qb, Mm, Dd, Dd);
    gemm_mma_kernel<<<ggrid, 256>>>(x, Wk, bk, nullptr, Kb, Mm, Dd, Dd);
    gemm_mma_kernel<<<ggrid, 256>>>(x, Wv, bv, nullptr, Vb, Mm, Dd, Dd);

    dim3 agrid(Nn / 128, Hh, Bb);     // (16, 8, 4)
    attn_mma_kernel<<<agrid, 128, ATTN_SMEM_BYTES>>>(Qb, Kb, Vb, adj, Hb);

    gemm_mma_kernel<<<ggrid, 256>>>(Hb, Wo, bo, x, Yb, Mm, Dd, Dd);

    ln_kernel<<<Mm, 128>>>(Yb, gamma, beta, out);
}